// round 15
// baseline (speedup 1.0000x reference)
#include <cuda_runtime.h>
#include <math.h>
#include <stdint.h>

#define NB 131072
#define ND 512
#define NS 64
#define NH 128
#define NCHUNK 128
#define CHUNK_ROWS (NB / NCHUNK)   /* 1024 */

// ---- scratch (static device globals; no runtime allocation) ----
static __device__ float g_h[(size_t)NB * NH];             // relu hidden (tf32-rounded)
static __device__ float g_w[(size_t)NB * NS];             // softmax weights (tf32-rounded)
static __device__ float g_upd[(size_t)NB * ND];           // tanh updates (tf32-rounded)
static __device__ float g_part[(size_t)NCHUNK * NS * ND]; // split-K partials
static __device__ float g_w1T[(size_t)NH * ND];           // [128][512] tf32
static __device__ float g_refT[(size_t)ND * NS];          // [512][64] tf32
static __device__ float g_w2T[(size_t)NS * NH];           // [64][128] tf32
static __device__ float g_bt[(size_t)ND * 576];           // [512 n][576 k] = [Wu1^T | RW^T] tf32
static __device__ float g_rw[(size_t)NS * ND];            // RW = ref @ Wu2  [64][512] f32

// ============================================================
// helpers
// ============================================================
__device__ __forceinline__ float f2tf32f(float x) {
  uint32_t r;
  asm("cvt.rna.tf32.f32 %0, %1;" : "=r"(r) : "f"(x));
  return __uint_as_float(r);
}
__device__ __forceinline__ void mma_tf32(float c[4], const uint32_t a[4],
                                         const uint32_t b[2]) {
  asm volatile(
      "mma.sync.aligned.m16n8k8.row.col.f32.tf32.tf32.f32 "
      "{%0,%1,%2,%3}, {%4,%5,%6,%7}, {%8,%9}, {%0,%1,%2,%3};"
      : "+f"(c[0]), "+f"(c[1]), "+f"(c[2]), "+f"(c[3])
      : "r"(a[0]), "r"(a[1]), "r"(a[2]), "r"(a[3]), "r"(b[0]), "r"(b[1]));
}
__device__ __forceinline__ void ldsm4(uint32_t r[4], uint32_t addr) {
  asm volatile("ldmatrix.sync.aligned.m8n8.x4.shared.b16 {%0,%1,%2,%3}, [%4];"
               : "=r"(r[0]), "=r"(r[1]), "=r"(r[2]), "=r"(r[3]) : "r"(addr));
}
template <int ACT> __device__ __forceinline__ float actf(float x) {
  if (ACT == 1) return x > 0.f ? x : 0.f;
  if (ACT == 2) return tanhf(x);
  return x;
}
#define CP_A16(dst, src)                                              \
  asm volatile("cp.async.cg.shared.global [%0], [%1], 16;"            \
               :: "r"(dst), "l"(__cvta_generic_to_global(src)) : "memory")
#define CP_COMMIT() asm volatile("cp.async.commit_group;" ::: "memory")
#define CP_WAIT0() asm volatile("cp.async.wait_group 0;" ::: "memory")
#define CP_WAIT1() asm volatile("cp.async.wait_group 1;" ::: "memory")

__device__ __forceinline__ uint32_t smem_u32(const void* p) {
  uint32_t a;
  asm("{ .reg .u64 t; cvta.to.shared.u64 t, %1; cvt.u32.u64 %0, t; }"
      : "=r"(a) : "l"(p));
  return a;
}

// ============================================================
// 32x32 transpose + tf32 round: dst[c*dst_stride + r] = tf32(src[r][c])
// ============================================================
__global__ void k_transpose(const float* __restrict__ src, float* __restrict__ dst,
                            int R, int C, int dst_stride) {
  __shared__ float t[32][33];
  int c0 = blockIdx.x * 32, r0 = blockIdx.y * 32;
  int x = threadIdx.x, y = threadIdx.y;
#pragma unroll
  for (int i = 0; i < 32; i += 8)
    t[y + i][x] = src[(size_t)(r0 + y + i) * C + c0 + x];
  __syncthreads();
#pragma unroll
  for (int i = 0; i < 32; i += 8)
    dst[(size_t)(c0 + y + i) * dst_stride + r0 + x] = f2tf32f(t[x][y + i]);
}

// ============================================================
// RW = ref @ Wu2  (f32 FFMA; tiny: 64x512x512)
// ============================================================
__global__ __launch_bounds__(256) void k_rw(
    const float* __restrict__ REF, const float* __restrict__ WU,
    float* __restrict__ RW) {
  __shared__ float rs[64][17];
  __shared__ float us[16][68];
  const int tid = threadIdx.x;
  const int n0 = blockIdx.x * 64;
  const int si = (tid >> 4) * 4, ni = (tid & 15) * 4;
  float acc[4][4];
#pragma unroll
  for (int i = 0; i < 4; i++)
#pragma unroll
    for (int j = 0; j < 4; j++) acc[i][j] = 0.f;

  for (int k0 = 0; k0 < 512; k0 += 16) {
    {
      int s = tid >> 2, c4 = (tid & 3) * 4;
      float4 v = *(const float4*)(REF + (size_t)s * 512 + k0 + c4);
      rs[s][c4] = v.x; rs[s][c4 + 1] = v.y; rs[s][c4 + 2] = v.z; rs[s][c4 + 3] = v.w;
    }
    {
      int r = tid >> 4, c4 = (tid & 15) * 4;
      float4 v = *(const float4*)(WU + (size_t)(512 + k0 + r) * 512 + n0 + c4);
      us[r][c4] = v.x; us[r][c4 + 1] = v.y; us[r][c4 + 2] = v.z; us[r][c4 + 3] = v.w;
    }
    __syncthreads();
#pragma unroll
    for (int kk = 0; kk < 16; kk++) {
#pragma unroll
      for (int i = 0; i < 4; i++) {
        float r = rs[si + i][kk];
#pragma unroll
        for (int j = 0; j < 4; j++) acc[i][j] = fmaf(r, us[kk][ni + j], acc[i][j]);
      }
    }
    __syncthreads();
  }
#pragma unroll
  for (int i = 0; i < 4; i++)
#pragma unroll
    for (int j = 0; j < 4; j++)
      RW[(size_t)(si + i) * 512 + n0 + ni + j] = acc[i][j];
}

// ============================================================
// tf32 mma.sync GEMM (K1, K4'): cp.async 3-stage, ONE barrier per chunk.
// Dynamic smem: 3 x (A 10240 + B 10240) = 61440 B.
// ============================================================
template <int ACT, int KTOT, bool ASPLIT, bool CVT_A>
__global__ __launch_bounds__(256, 2) void gemm_mma(
    const float* __restrict__ A0, const float* __restrict__ A1,
    int a_stride, int a1_stride,
    const float* __restrict__ BT, const float* __restrict__ bias,
    float* __restrict__ OUT, int o_stride) {
  extern __shared__ char dsm[];
  const uint32_t sA = smem_u32(dsm);          // 3 stages x 10240
  const uint32_t sB = sA + 3 * 10240;         // 3 stages x 10240
  const int tid = threadIdx.x, wid = tid >> 5, lane = tid & 31;
  const int n0 = blockIdx.x * 128;
  const int m0 = blockIdx.y * 128;
  const int wm = (wid & 3) * 32;
  const int wn = (wid >> 2) * 64;
  const int g = lane >> 2, t = lane & 3;
  const int lrow = ((lane >> 3) & 1) * 8 + (lane & 7);
  const int lcol = (lane >> 4) * 4;
  const int row_l = tid >> 2;
  const int c4_l = (tid & 3) * 4;

  float acc[2][8][4];
#pragma unroll
  for (int mt = 0; mt < 2; mt++)
#pragma unroll
    for (int nt = 0; nt < 8; nt++)
#pragma unroll
      for (int r = 0; r < 4; r++) acc[mt][nt][r] = 0.f;

  auto load_tiles = [&](int c, int st) {
    const int k0 = c * 16;
    const float* Asrc = (!ASPLIT || k0 < 512) ? A0 : A1;
    const int ko = (!ASPLIT || k0 < 512) ? k0 : k0 - 512;
    const int ast = (!ASPLIT || k0 < 512) ? a_stride : a1_stride;
    const uint32_t da = sA + (uint32_t)st * 10240;
    const uint32_t db = sB + (uint32_t)st * 10240;
#pragma unroll
    for (int l = 0; l < 2; l++) {
      const int row = row_l + l * 64;
      CP_A16(da + (uint32_t)(row * 20 + c4_l) * 4,
             Asrc + (size_t)(m0 + row) * ast + ko + c4_l);
      CP_A16(db + (uint32_t)(row * 20 + c4_l) * 4,
             BT + (size_t)(n0 + row) * KTOT + k0 + c4_l);
    }
  };

  constexpr int NCH = KTOT / 16;
  load_tiles(0, 0);
  CP_COMMIT();
  if (NCH > 1) { load_tiles(1, 1); CP_COMMIT(); }
#pragma unroll 1
  for (int c = 0; c < NCH; c++) {
    const int st = c % 3;
    if (c + 2 < NCH) CP_WAIT1(); else CP_WAIT0();
    __syncthreads();
    if (c + 2 < NCH) { load_tiles(c + 2, (c + 2) % 3); CP_COMMIT(); }
    const uint32_t ab = sA + (uint32_t)st * 10240;
    const uint32_t bb = sB + (uint32_t)st * 10240;
#pragma unroll
    for (int ks = 0; ks < 2; ks++) {
      const int kk = ks * 8;
      uint32_t a[2][4], b[8][2];
#pragma unroll
      for (int mt = 0; mt < 2; mt++) {
        ldsm4(a[mt], ab + (uint32_t)((wm + mt * 16 + lrow) * 20 + kk + lcol) * 4);
        if (CVT_A) {
#pragma unroll
          for (int r = 0; r < 4; r++)
            a[mt][r] = __float_as_uint(f2tf32f(__uint_as_float(a[mt][r])));
        }
      }
#pragma unroll
      for (int p = 0; p < 4; p++) {
        uint32_t t4[4];
        ldsm4(t4, bb + (uint32_t)((wn + p * 16 + lrow) * 20 + kk + lcol) * 4);
        b[2 * p][0] = t4[0]; b[2 * p + 1][0] = t4[1];
        b[2 * p][1] = t4[2]; b[2 * p + 1][1] = t4[3];
      }
#pragma unroll
      for (int mt = 0; mt < 2; mt++)
#pragma unroll
        for (int nt = 0; nt < 8; nt++) mma_tf32(acc[mt][nt], a[mt], b[nt]);
    }
  }

#pragma unroll
  for (int mt = 0; mt < 2; mt++) {
#pragma unroll
    for (int nt = 0; nt < 8; nt++) {
      const int row = m0 + wm + mt * 16 + g;
      const int col = n0 + wn + nt * 8 + t * 2;
      float b0 = 0.f, b1 = 0.f;
      if (bias) { b0 = bias[col]; b1 = bias[col + 1]; }
      float r0 = actf<ACT>(acc[mt][nt][0] + b0);
      float r1 = actf<ACT>(acc[mt][nt][1] + b1);
      float r2 = actf<ACT>(acc[mt][nt][2] + b0);
      float r3 = actf<ACT>(acc[mt][nt][3] + b1);
      if (ACT != 0) { r0 = f2tf32f(r0); r1 = f2tf32f(r1); r2 = f2tf32f(r2); r3 = f2tf32f(r3); }
      *(float2*)(OUT + (size_t)row * o_stride + col) = make_float2(r0, r1);
      *(float2*)(OUT + (size_t)(row + 8) * o_stride + col) = make_float2(r2, r3);
    }
  }
}

// ============================================================
// k3_select: selected = w @ ref.  One CTA per 128-row block (grid 1024).
// ============================================================
__global__ __launch_bounds__(256, 2) void k3_select(
    const float* __restrict__ REFT, float* __restrict__ OUT) {
  extern __shared__ char dsm[];
  const uint32_t sA = smem_u32(dsm);           // [128][68]
  const uint32_t sB = sA + 34816;              // 2 x [128][68]
  const int tid = threadIdx.x, wid = tid >> 5, lane = tid & 31;
  const int m0 = blockIdx.x * 128;
  const int wm = (wid & 3) * 32;
  const int wn = (wid >> 2) * 64;
  const int g = lane >> 2, t = lane & 3;
  const int lrow = ((lane >> 3) & 1) * 8 + (lane & 7);
  const int lcol = (lane >> 4) * 4;

#pragma unroll
  for (int i = 0; i < 8; i++) {
    const int idx = tid + i * 256;
    const int row = idx >> 4, c4 = (idx & 15) * 4;
    CP_A16(sA + (uint32_t)(row * 68 + c4) * 4, g_w + (size_t)(m0 + row) * 64 + c4);
  }
  auto loadB = [&](int nc, int buf) {
#pragma unroll
    for (int i = 0; i < 8; i++) {
      const int idx = tid + i * 256;
      const int row = idx >> 4, c4 = (idx & 15) * 4;
      CP_A16(sB + (uint32_t)buf * 34816 + (uint32_t)(row * 68 + c4) * 4,
             REFT + (size_t)(nc * 128 + row) * 64 + c4);
    }
  };
  loadB(0, 0);
  CP_COMMIT();

#pragma unroll 1
  for (int nc = 0; nc < 4; nc++) {
    const int buf = nc & 1;
    if (nc + 1 < 4) { loadB(nc + 1, buf ^ 1); CP_COMMIT(); CP_WAIT1(); }
    else CP_WAIT0();
    __syncthreads();

    float acc[2][8][4];
#pragma unroll
    for (int mt = 0; mt < 2; mt++)
#pragma unroll
      for (int nt = 0; nt < 8; nt++)
#pragma unroll
        for (int r = 0; r < 4; r++) acc[mt][nt][r] = 0.f;

    const uint32_t bb = sB + (uint32_t)buf * 34816;
#pragma unroll
    for (int ks = 0; ks < 8; ks++) {
      const int kk = ks * 8;
      uint32_t a[2][4], b[8][2];
#pragma unroll
      for (int mt = 0; mt < 2; mt++)
        ldsm4(a[mt], sA + (uint32_t)((wm + mt * 16 + lrow) * 68 + kk + lcol) * 4);
#pragma unroll
      for (int p = 0; p < 4; p++) {
        uint32_t t4[4];
        ldsm4(t4, bb + (uint32_t)((wn + p * 16 + lrow) * 68 + kk + lcol) * 4);
        b[2 * p][0] = t4[0]; b[2 * p + 1][0] = t4[1];
        b[2 * p][1] = t4[2]; b[2 * p + 1][1] = t4[3];
      }
#pragma unroll
      for (int mt = 0; mt < 2; mt++)
#pragma unroll
        for (int nt = 0; nt < 8; nt++) mma_tf32(acc[mt][nt], a[mt], b[nt]);
    }
#pragma unroll
    for (int mt = 0; mt < 2; mt++)
#pragma unroll
      for (int nt = 0; nt < 8; nt++) {
        const int row = m0 + wm + mt * 16 + g;
        const int col = nc * 128 + wn + nt * 8 + t * 2;
        *(float2*)(OUT + (size_t)row * 512 + col) =
            make_float2(acc[mt][nt][0], acc[mt][nt][1]);
        *(float2*)(OUT + (size_t)(row + 8) * 512 + col) =
            make_float2(acc[mt][nt][2], acc[mt][nt][3]);
      }
    __syncthreads();
  }
}

// ============================================================
// K2: w = softmax(h @ W2 + b2) via tf32 mma + ldmatrix, softmax in regs.
// ============================================================
__global__ __launch_bounds__(256, 2) void k2_mma(
    const float* __restrict__ W2T, const float* __restrict__ b2) {
  __shared__ float As[2][128][20];
  __shared__ float Bs[2][64][20];
  const int tid = threadIdx.x, wid = tid >> 5, lane = tid & 31;
  const int m0 = blockIdx.x * 128;
  const int g = lane >> 2, t = lane & 3;
  const int lrow = ((lane >> 3) & 1) * 8 + (lane & 7);
  const int lcol = (lane >> 4) * 4;
  const uint32_t sA = smem_u32(&As[0][0][0]);
  const uint32_t sB = smem_u32(&Bs[0][0][0]);

  float acc[8][4];
#pragma unroll
  for (int nt = 0; nt < 8; nt++)
#pragma unroll
    for (int r = 0; r < 4; r++) acc[nt][r] = 0.f;

  auto load = [&](int c, int buf) {
    const int k0 = c * 16;
    const int rowa = tid >> 2, c4 = (tid & 3) * 4;
#pragma unroll
    for (int l = 0; l < 2; l++) {
      const int row = rowa + l * 64;
      CP_A16(sA + (uint32_t)buf * (128 * 20 * 4) + (uint32_t)(row * 20 + c4) * 4,
             g_h + (size_t)(m0 + row) * 128 + k0 + c4);
    }
    if (rowa < 64)
      CP_A16(sB + (uint32_t)buf * (64 * 20 * 4) + (uint32_t)(rowa * 20 + c4) * 4,
             W2T + (size_t)rowa * 128 + k0 + c4);
  };

  load(0, 0);
  CP_COMMIT();
#pragma unroll 1
  for (int c = 0; c < 8; c++) {
    const int buf = c & 1;
    if (c + 1 < 8) { load(c + 1, buf ^ 1); CP_COMMIT(); CP_WAIT1(); }
    else CP_WAIT0();
    __syncthreads();
    const uint32_t ab = sA + (uint32_t)buf * (128 * 20 * 4);
    const uint32_t bb = sB + (uint32_t)buf * (64 * 20 * 4);
#pragma unroll
    for (int ks = 0; ks < 2; ks++) {
      const int kk = ks * 8;
      uint32_t a[4], b[8][2];
      ldsm4(a, ab + (uint32_t)((wid * 16 + lrow) * 20 + kk + lcol) * 4);
#pragma unroll
      for (int p = 0; p < 4; p++) {
        uint32_t t4[4];
        ldsm4(t4, bb + (uint32_t)((p * 16 + lrow) * 20 + kk + lcol) * 4);
        b[2 * p][0] = t4[0]; b[2 * p + 1][0] = t4[1];
        b[2 * p][1] = t4[2]; b[2 * p + 1][1] = t4[3];
      }
#pragma unroll
      for (int nt = 0; nt < 8; nt++) mma_tf32(acc[nt], a, b[nt]);
    }
    __syncthreads();
  }

#pragma unroll
  for (int nt = 0; nt < 8; nt++) {
    float2 bb = *(const float2*)(b2 + nt * 8 + t * 2);
    acc[nt][0] += bb.x; acc[nt][1] += bb.y;
    acc[nt][2] += bb.x; acc[nt][3] += bb.y;
  }
  float m0v = -1e30f, m1v = -1e30f;
#pragma unroll
  for (int nt = 0; nt < 8; nt++) {
    m0v = fmaxf(m0v, fmaxf(acc[nt][0], acc[nt][1]));
    m1v = fmaxf(m1v, fmaxf(acc[nt][2], acc[nt][3]));
  }
#pragma unroll
  for (int o = 1; o <= 2; o <<= 1) {
    m0v = fmaxf(m0v, __shfl_xor_sync(~0u, m0v, o));
    m1v = fmaxf(m1v, __shfl_xor_sync(~0u, m1v, o));
  }
  float s0 = 0.f, s1 = 0.f;
#pragma unroll
  for (int nt = 0; nt < 8; nt++) {
    acc[nt][0] = __expf(acc[nt][0] - m0v); s0 += acc[nt][0];
    acc[nt][1] = __expf(acc[nt][1] - m0v); s0 += acc[nt][1];
    acc[nt][2] = __expf(acc[nt][2] - m1v); s1 += acc[nt][2];
    acc[nt][3] = __expf(acc[nt][3] - m1v); s1 += acc[nt][3];
  }
#pragma unroll
  for (int o = 1; o <= 2; o <<= 1) {
    s0 += __shfl_xor_sync(~0u, s0, o);
    s1 += __shfl_xor_sync(~0u, s1, o);
  }
  const float i0 = 1.f / s0, i1 = 1.f / s1;
  const int r0 = m0 + wid * 16 + g;
#pragma unroll
  for (int nt = 0; nt < 8; nt++) {
    const int col = nt * 8 + t * 2;
    *(float2*)(g_w + (size_t)r0 * 64 + col) =
        make_float2(f2tf32f(acc[nt][0] * i0), f2tf32f(acc[nt][1] * i0));
    *(float2*)(g_w + (size_t)(r0 + 8) * 64 + col) =
        make_float2(f2tf32f(acc[nt][2] * i1), f2tf32f(acc[nt][3] * i1));
  }
}

// ============================================================
// K5a: split-K partials of w^T @ updates via tf32 mma.
// 3-stage cp.async, one barrier per chunk.
// ============================================================
__global__ __launch_bounds__(256) void k5a_partials() {
  const int dq    = blockIdx.x & 3;
  const int chunk = blockIdx.x >> 2;
  const int d0 = dq * 128;
  const int b0 = chunk * CHUNK_ROWS;
  __shared__ float wt[3][16][68];
  __shared__ float ut[3][16][132];
  const int tid = threadIdx.x, wid = tid >> 5, lane = tid & 31;
  const int sw = (wid & 1) * 32, dw = (wid >> 1) * 32;
  const int g = lane >> 2, t = lane & 3;
  const uint32_t sW = smem_u32(&wt[0][0][0]);
  const uint32_t sU = smem_u32(&ut[0][0][0]);

  float acc[2][4][4];
#pragma unroll
  for (int mt = 0; mt < 2; mt++)
#pragma unroll
    for (int nt = 0; nt < 4; nt++)
#pragma unroll
      for (int r = 0; r < 4; r++) acc[mt][nt][r] = 0.f;

  auto load = [&](int c, int st) {
    const int k0 = c * 16;
    {
      const int row = tid >> 4, c4 = (tid & 15) * 4;
      CP_A16(sW + (uint32_t)st * (16 * 68 * 4) + (uint32_t)(row * 68 + c4) * 4,
             g_w + (size_t)(b0 + k0 + row) * 64 + c4);
    }
#pragma unroll
    for (int l = 0; l < 2; l++) {
      const int lin = tid + l * 256;
      const int row = lin >> 5, c4 = (lin & 31) * 4;
      CP_A16(sU + (uint32_t)st * (16 * 132 * 4) + (uint32_t)(row * 132 + c4) * 4,
             g_upd + (size_t)(b0 + k0 + row) * 512 + d0 + c4);
    }
  };

  constexpr int NCH = CHUNK_ROWS / 16;
  load(0, 0);
  CP_COMMIT();
  load(1, 1);
  CP_COMMIT();
#pragma unroll 1
  for (int c = 0; c < NCH; c++) {
    const int st = c % 3;
    if (c + 2 < NCH) CP_WAIT1(); else CP_WAIT0();
    __syncthreads();
    if (c + 2 < NCH) { load(c + 2, (c + 2) % 3); CP_COMMIT(); }
#pragma unroll
    for (int ks = 0; ks < 2; ks++) {
      const int kk = ks * 8;
      uint32_t a[2][4], b[4][2];
#pragma unroll
      for (int mt = 0; mt < 2; mt++) {
        const int sb = sw + mt * 16;
        a[mt][0] = __float_as_uint(wt[st][kk + t][sb + g]);
        a[mt][1] = __float_as_uint(wt[st][kk + t][sb + 8 + g]);
        a[mt][2] = __float_as_uint(wt[st][kk + t + 4][sb + g]);
        a[mt][3] = __float_as_uint(wt[st][kk + t + 4][sb + 8 + g]);
      }
#pragma unroll
      for (int nt = 0; nt < 4; nt++) {
        const int db = dw + nt * 8;
        b[nt][0] = __float_as_uint(ut[st][kk + t][db + g]);
        b[nt][1] = __float_as_uint(ut[st][kk + t + 4][db + g]);
      }
#pragma unroll
      for (int mt = 0; mt < 2; mt++)
#pragma unroll
        for (int nt = 0; nt < 4; nt++) mma_tf32(acc[mt][nt], a[mt], b[nt]);
    }
  }

  float* p = g_part + (size_t)chunk * (NS * ND);
#pragma unroll
  for (int mt = 0; mt < 2; mt++) {
#pragma unroll
    for (int nt = 0; nt < 4; nt++) {
      const int s = sw + mt * 16 + g;
      const int d = d0 + dw + nt * 8 + t * 2;
      *(float2*)(p + (size_t)s * 512 + d) = make_float2(acc[mt][nt][0], acc[mt][nt][1]);
      *(float2*)(p + (size_t)(s + 8) * 512 + d) = make_float2(acc[mt][nt][2], acc[mt][nt][3]);
    }
  }
}

// ============================================================
// K5b: new_ref = ref + 0.01 * sum(partials)   (deterministic order)
// ============================================================
__global__ __launch_bounds__(256) void k5b_reduce(
    const float* __restrict__ REF, float* __restrict__ OUT_REF) {
  const int idx = blockIdx.x * 256 + threadIdx.x;
  float s = 0.f;
#pragma unroll 8
  for (int c = 0; c < NCHUNK; c++) s += g_part[(size_t)c * (NS * ND) + idx];
  OUT_REF[idx] = REF[idx] + 0.01f * s;
}

// ============================================================
extern "C" void kernel_launch(void* const* d_in, const int* in_sizes, int n_in,
                              void* d_out, int out_size) {
  const float* X   = (const float*)d_in[0];
  const float* REF = (const float*)d_in[1];
  const float* W1  = (const float*)d_in[2];
  const float* b1  = (const float*)d_in[3];
  const float* W2  = (const float*)d_in[4];
  const float* b2  = (const float*)d_in[5];
  const float* WU  = (const float*)d_in[6];
  const float* bu  = (const float*)d_in[7];

  float* out_sel = (float*)d_out;
  float* out_ref = (float*)d_out + (size_t)NB * ND;

  float *w1T, *refT, *w2T, *bt, *rw, *h, *w, *upd;
  cudaGetSymbolAddress((void**)&w1T, g_w1T);
  cudaGetSymbolAddress((void**)&refT, g_refT);
  cudaGetSymbolAddress((void**)&w2T, g_w2T);
  cudaGetSymbolAddress((void**)&bt, g_bt);
  cudaGetSymbolAddress((void**)&rw, g_rw);
  cudaGetSymbolAddress((void**)&h, g_h);
  cudaGetSymbolAddress((void**)&w, g_w);
  cudaGetSymbolAddress((void**)&upd, g_upd);

  static int smem_set = 0;
  if (!smem_set) {
    cudaFuncSetAttribute(k3_select, cudaFuncAttributeMaxDynamicSharedMemorySize, 104448);
    cudaFuncSetAttribute(gemm_mma<1, 512, false, true>,
                         cudaFuncAttributeMaxDynamicSharedMemorySize, 61440);
    cudaFuncSetAttribute(gemm_mma<2, 576, true, true>,
                         cudaFuncAttributeMaxDynamicSharedMemorySize, 61440);
    smem_set = 1;
  }

  dim3 tb(32, 8);
  // weight preprocessing (all tiny)
  k_transpose<<<dim3(4, 16), tb>>>(W1, w1T, 512, 128, 512);    // W1^T tf32
  k_transpose<<<dim3(16, 2), tb>>>(REF, refT, 64, 512, 64);    // ref^T tf32
  k_transpose<<<dim3(2, 4), tb>>>(W2, w2T, 128, 64, 128);      // W2^T tf32
  k_transpose<<<dim3(16, 16), tb>>>(WU, bt, 512, 512, 576);    // Wu1^T -> bt[:, 0:512]
  k_rw<<<8, 256>>>(REF, WU, rw);                               // RW = ref @ Wu2 (f32)
  k_transpose<<<dim3(16, 2), tb>>>(rw, bt + 512, 64, 512, 576);// RW^T -> bt[:, 512:576]

  // K1: h = relu(X @ W1 + b1)   (tf32-rounded store)
  gemm_mma<1, 512, false, true><<<dim3(1, NB / 128), 256, 61440>>>(
      X, nullptr, 512, 0, w1T, b1, h, 128);
  // K2: w = softmax(h @ W2 + b2)
  k2_mma<<<NB / 128, 256>>>(w2T, b2);
  // K3: selected = w @ ref   (one CTA per row-block, n-loop)
  k3_select<<<NB / 128, 256, 104448>>>(refT, out_sel);
  // K4': updates = tanh([X | w] @ [Wu1; RW] + bu)   K=576
  gemm_mma<2, 576, true, true><<<dim3(4, NB / 128), 256, 61440>>>(
      X, w, 512, 64, bt, bu, upd, 512);
  // K5: ref update (deterministic split-K, tensor core)
  k5a_partials<<<NCHUNK * 4, 256>>>();
  k5b_reduce<<<(NS * ND) / 256, 256>>>(REF, out_ref);
}

// round 16
// speedup vs baseline: 1.0160x; 1.0160x over previous
#include <cuda_runtime.h>
#include <math.h>
#include <stdint.h>

#define NB 131072
#define ND 512
#define NS 64
#define NH 128
#define NCHUNK 128
#define CHUNK_ROWS (NB / NCHUNK)   /* 1024 */

// ---- scratch (static device globals; no runtime allocation) ----
static __device__ float g_h[(size_t)NB * NH];             // relu hidden (tf32-rounded)
static __device__ float g_w[(size_t)NB * NS];             // softmax weights (tf32-rounded)
static __device__ float g_upd[(size_t)NB * ND];           // tanh updates (tf32-rounded)
static __device__ float g_part[(size_t)NCHUNK * NS * ND]; // split-K partials
static __device__ float g_w1T[(size_t)NH * ND];           // [128][512] tf32
static __device__ float g_refT[(size_t)ND * NS];          // [512][64] tf32
static __device__ float g_w2T[(size_t)NS * NH];           // [64][128] tf32
static __device__ float g_bt[(size_t)ND * 576];           // [512 n][576 k] = [Wu1^T | RW^T] tf32
static __device__ float g_rw[(size_t)NS * ND];            // RW = ref @ Wu2  [64][512] f32

// ============================================================
// helpers
// ============================================================
__device__ __forceinline__ float f2tf32f(float x) {
  uint32_t r;
  asm("cvt.rna.tf32.f32 %0, %1;" : "=r"(r) : "f"(x));
  return __uint_as_float(r);
}
__device__ __forceinline__ void mma_tf32(float c[4], const uint32_t a[4],
                                         const uint32_t b[2]) {
  asm volatile(
      "mma.sync.aligned.m16n8k8.row.col.f32.tf32.tf32.f32 "
      "{%0,%1,%2,%3}, {%4,%5,%6,%7}, {%8,%9}, {%0,%1,%2,%3};"
      : "+f"(c[0]), "+f"(c[1]), "+f"(c[2]), "+f"(c[3])
      : "r"(a[0]), "r"(a[1]), "r"(a[2]), "r"(a[3]), "r"(b[0]), "r"(b[1]));
}
__device__ __forceinline__ void ldsm4(uint32_t r[4], uint32_t addr) {
  asm volatile("ldmatrix.sync.aligned.m8n8.x4.shared.b16 {%0,%1,%2,%3}, [%4];"
               : "=r"(r[0]), "=r"(r[1]), "=r"(r[2]), "=r"(r[3]) : "r"(addr));
}
template <int ACT> __device__ __forceinline__ float actf(float x) {
  if (ACT == 1) return x > 0.f ? x : 0.f;
  if (ACT == 2) return tanhf(x);
  return x;
}
#define CP_A16(dst, src)                                              \
  asm volatile("cp.async.cg.shared.global [%0], [%1], 16;"            \
               :: "r"(dst), "l"(__cvta_generic_to_global(src)) : "memory")
#define CP_COMMIT() asm volatile("cp.async.commit_group;" ::: "memory")
#define CP_WAIT0() asm volatile("cp.async.wait_group 0;" ::: "memory")
#define CP_WAIT1() asm volatile("cp.async.wait_group 1;" ::: "memory")

__device__ __forceinline__ uint32_t smem_u32(const void* p) {
  uint32_t a;
  asm("{ .reg .u64 t; cvta.to.shared.u64 t, %1; cvt.u32.u64 %0, t; }"
      : "=r"(a) : "l"(p));
  return a;
}

// ============================================================
// 32x32 transpose + tf32 round: dst[c*dst_stride + r] = tf32(src[r][c])
// ============================================================
__global__ void k_transpose(const float* __restrict__ src, float* __restrict__ dst,
                            int R, int C, int dst_stride) {
  __shared__ float t[32][33];
  int c0 = blockIdx.x * 32, r0 = blockIdx.y * 32;
  int x = threadIdx.x, y = threadIdx.y;
#pragma unroll
  for (int i = 0; i < 32; i += 8)
    t[y + i][x] = src[(size_t)(r0 + y + i) * C + c0 + x];
  __syncthreads();
#pragma unroll
  for (int i = 0; i < 32; i += 8)
    dst[(size_t)(c0 + y + i) * dst_stride + r0 + x] = f2tf32f(t[x][y + i]);
}

// ============================================================
// RW = ref @ Wu2  (f32 FFMA; tiny: 64x512x512)
// ============================================================
__global__ __launch_bounds__(256) void k_rw(
    const float* __restrict__ REF, const float* __restrict__ WU,
    float* __restrict__ RW) {
  __shared__ float rs[64][17];
  __shared__ float us[16][68];
  const int tid = threadIdx.x;
  const int n0 = blockIdx.x * 64;
  const int si = (tid >> 4) * 4, ni = (tid & 15) * 4;
  float acc[4][4];
#pragma unroll
  for (int i = 0; i < 4; i++)
#pragma unroll
    for (int j = 0; j < 4; j++) acc[i][j] = 0.f;

  for (int k0 = 0; k0 < 512; k0 += 16) {
    {
      int s = tid >> 2, c4 = (tid & 3) * 4;
      float4 v = *(const float4*)(REF + (size_t)s * 512 + k0 + c4);
      rs[s][c4] = v.x; rs[s][c4 + 1] = v.y; rs[s][c4 + 2] = v.z; rs[s][c4 + 3] = v.w;
    }
    {
      int r = tid >> 4, c4 = (tid & 15) * 4;
      float4 v = *(const float4*)(WU + (size_t)(512 + k0 + r) * 512 + n0 + c4);
      us[r][c4] = v.x; us[r][c4 + 1] = v.y; us[r][c4 + 2] = v.z; us[r][c4 + 3] = v.w;
    }
    __syncthreads();
#pragma unroll
    for (int kk = 0; kk < 16; kk++) {
#pragma unroll
      for (int i = 0; i < 4; i++) {
        float r = rs[si + i][kk];
#pragma unroll
        for (int j = 0; j < 4; j++) acc[i][j] = fmaf(r, us[kk][ni + j], acc[i][j]);
      }
    }
    __syncthreads();
  }
#pragma unroll
  for (int i = 0; i < 4; i++)
#pragma unroll
    for (int j = 0; j < 4; j++)
      RW[(size_t)(si + i) * 512 + n0 + ni + j] = acc[i][j];
}

// ============================================================
// tf32 mma.sync GEMM (K1, K4'): cp.async 3-stage, CUTLASS order:
// per chunk: issue(c+2) -> compute(c) -> wait<=1 -> ONE sync.
// Dynamic smem: 3 x (A 10240 + B 10240) = 61440 B.
// ============================================================
template <int ACT, int KTOT, bool ASPLIT, bool CVT_A>
__global__ __launch_bounds__(256, 2) void gemm_mma(
    const float* __restrict__ A0, const float* __restrict__ A1,
    int a_stride, int a1_stride,
    const float* __restrict__ BT, const float* __restrict__ bias,
    float* __restrict__ OUT, int o_stride) {
  extern __shared__ char dsm[];
  const uint32_t sA = smem_u32(dsm);          // 3 stages x 10240
  const uint32_t sB = sA + 3 * 10240;         // 3 stages x 10240
  const int tid = threadIdx.x, wid = tid >> 5, lane = tid & 31;
  const int n0 = blockIdx.x * 128;
  const int m0 = blockIdx.y * 128;
  const int wm = (wid & 3) * 32;
  const int wn = (wid >> 2) * 64;
  const int g = lane >> 2, t = lane & 3;
  const int lrow = ((lane >> 3) & 1) * 8 + (lane & 7);
  const int lcol = (lane >> 4) * 4;
  const int row_l = tid >> 2;
  const int c4_l = (tid & 3) * 4;

  float acc[2][8][4];
#pragma unroll
  for (int mt = 0; mt < 2; mt++)
#pragma unroll
    for (int nt = 0; nt < 8; nt++)
#pragma unroll
      for (int r = 0; r < 4; r++) acc[mt][nt][r] = 0.f;

  auto load_tiles = [&](int c, int st) {
    const int k0 = c * 16;
    const float* Asrc = (!ASPLIT || k0 < 512) ? A0 : A1;
    const int ko = (!ASPLIT || k0 < 512) ? k0 : k0 - 512;
    const int ast = (!ASPLIT || k0 < 512) ? a_stride : a1_stride;
    const uint32_t da = sA + (uint32_t)st * 10240;
    const uint32_t db = sB + (uint32_t)st * 10240;
#pragma unroll
    for (int l = 0; l < 2; l++) {
      const int row = row_l + l * 64;
      CP_A16(da + (uint32_t)(row * 20 + c4_l) * 4,
             Asrc + (size_t)(m0 + row) * ast + ko + c4_l);
      CP_A16(db + (uint32_t)(row * 20 + c4_l) * 4,
             BT + (size_t)(n0 + row) * KTOT + k0 + c4_l);
    }
  };

  constexpr int NCH = KTOT / 16;
  load_tiles(0, 0);
  CP_COMMIT();
  load_tiles(1, 1);
  CP_COMMIT();
  CP_WAIT1();            // group 0 complete
  __syncthreads();       // publish stage 0
#pragma unroll 1
  for (int c = 0; c < NCH; c++) {
    const int st = c % 3;
    // prefetch c+2 into stage (c+2)%3 — its readers (iter c-1) are past the
    // trailing sync of iter c-1, so the write is safe.
    if (c + 2 < NCH) { load_tiles(c + 2, (c + 2) % 3); CP_COMMIT(); }
    const uint32_t ab = sA + (uint32_t)st * 10240;
    const uint32_t bb = sB + (uint32_t)st * 10240;
#pragma unroll
    for (int ks = 0; ks < 2; ks++) {
      const int kk = ks * 8;
      uint32_t a[2][4], b[8][2];
#pragma unroll
      for (int mt = 0; mt < 2; mt++) {
        ldsm4(a[mt], ab + (uint32_t)((wm + mt * 16 + lrow) * 20 + kk + lcol) * 4);
        if (CVT_A) {
#pragma unroll
          for (int r = 0; r < 4; r++)
            a[mt][r] = __float_as_uint(f2tf32f(__uint_as_float(a[mt][r])));
        }
      }
#pragma unroll
      for (int p = 0; p < 4; p++) {
        uint32_t t4[4];
        ldsm4(t4, bb + (uint32_t)((wn + p * 16 + lrow) * 20 + kk + lcol) * 4);
        b[2 * p][0] = t4[0]; b[2 * p + 1][0] = t4[1];
        b[2 * p][1] = t4[2]; b[2 * p + 1][1] = t4[3];
      }
#pragma unroll
      for (int mt = 0; mt < 2; mt++)
#pragma unroll
        for (int nt = 0; nt < 8; nt++) mma_tf32(acc[mt][nt], a[mt], b[nt]);
    }
    // guarantee group c+1 complete, then publish for next iteration
    if (c + 1 < NCH) {
      if (c + 2 < NCH) CP_WAIT1(); else CP_WAIT0();
      __syncthreads();
    }
  }

#pragma unroll
  for (int mt = 0; mt < 2; mt++) {
#pragma unroll
    for (int nt = 0; nt < 8; nt++) {
      const int row = m0 + wm + mt * 16 + g;
      const int col = n0 + wn + nt * 8 + t * 2;
      float b0 = 0.f, b1 = 0.f;
      if (bias) { b0 = bias[col]; b1 = bias[col + 1]; }
      float r0 = actf<ACT>(acc[mt][nt][0] + b0);
      float r1 = actf<ACT>(acc[mt][nt][1] + b1);
      float r2 = actf<ACT>(acc[mt][nt][2] + b0);
      float r3 = actf<ACT>(acc[mt][nt][3] + b1);
      if (ACT != 0) { r0 = f2tf32f(r0); r1 = f2tf32f(r1); r2 = f2tf32f(r2); r3 = f2tf32f(r3); }
      *(float2*)(OUT + (size_t)row * o_stride + col) = make_float2(r0, r1);
      *(float2*)(OUT + (size_t)(row + 8) * o_stride + col) = make_float2(r2, r3);
    }
  }
}

// ============================================================
// k3_select: selected = w @ ref.  One CTA per 128-row block (grid 1024).
// ============================================================
__global__ __launch_bounds__(256, 2) void k3_select(
    const float* __restrict__ REFT, float* __restrict__ OUT) {
  extern __shared__ char dsm[];
  const uint32_t sA = smem_u32(dsm);           // [128][68]
  const uint32_t sB = sA + 34816;              // 2 x [128][68]
  const int tid = threadIdx.x, wid = tid >> 5, lane = tid & 31;
  const int m0 = blockIdx.x * 128;
  const int wm = (wid & 3) * 32;
  const int wn = (wid >> 2) * 64;
  const int g = lane >> 2, t = lane & 3;
  const int lrow = ((lane >> 3) & 1) * 8 + (lane & 7);
  const int lcol = (lane >> 4) * 4;

#pragma unroll
  for (int i = 0; i < 8; i++) {
    const int idx = tid + i * 256;
    const int row = idx >> 4, c4 = (idx & 15) * 4;
    CP_A16(sA + (uint32_t)(row * 68 + c4) * 4, g_w + (size_t)(m0 + row) * 64 + c4);
  }
  auto loadB = [&](int nc, int buf) {
#pragma unroll
    for (int i = 0; i < 8; i++) {
      const int idx = tid + i * 256;
      const int row = idx >> 4, c4 = (idx & 15) * 4;
      CP_A16(sB + (uint32_t)buf * 34816 + (uint32_t)(row * 68 + c4) * 4,
             REFT + (size_t)(nc * 128 + row) * 64 + c4);
    }
  };
  loadB(0, 0);
  CP_COMMIT();

#pragma unroll 1
  for (int nc = 0; nc < 4; nc++) {
    const int buf = nc & 1;
    if (nc + 1 < 4) { loadB(nc + 1, buf ^ 1); CP_COMMIT(); CP_WAIT1(); }
    else CP_WAIT0();
    __syncthreads();

    float acc[2][8][4];
#pragma unroll
    for (int mt = 0; mt < 2; mt++)
#pragma unroll
      for (int nt = 0; nt < 8; nt++)
#pragma unroll
        for (int r = 0; r < 4; r++) acc[mt][nt][r] = 0.f;

    const uint32_t bb = sB + (uint32_t)buf * 34816;
#pragma unroll
    for (int ks = 0; ks < 8; ks++) {
      const int kk = ks * 8;
      uint32_t a[2][4], b[8][2];
#pragma unroll
      for (int mt = 0; mt < 2; mt++)
        ldsm4(a[mt], sA + (uint32_t)((wm + mt * 16 + lrow) * 68 + kk + lcol) * 4);
#pragma unroll
      for (int p = 0; p < 4; p++) {
        uint32_t t4[4];
        ldsm4(t4, bb + (uint32_t)((wn + p * 16 + lrow) * 68 + kk + lcol) * 4);
        b[2 * p][0] = t4[0]; b[2 * p + 1][0] = t4[1];
        b[2 * p][1] = t4[2]; b[2 * p + 1][1] = t4[3];
      }
#pragma unroll
      for (int mt = 0; mt < 2; mt++)
#pragma unroll
        for (int nt = 0; nt < 8; nt++) mma_tf32(acc[mt][nt], a[mt], b[nt]);
    }
#pragma unroll
    for (int mt = 0; mt < 2; mt++)
#pragma unroll
      for (int nt = 0; nt < 8; nt++) {
        const int row = m0 + wm + mt * 16 + g;
        const int col = nc * 128 + wn + nt * 8 + t * 2;
        *(float2*)(OUT + (size_t)row * 512 + col) =
            make_float2(acc[mt][nt][0], acc[mt][nt][1]);
        *(float2*)(OUT + (size_t)(row + 8) * 512 + col) =
            make_float2(acc[mt][nt][2], acc[mt][nt][3]);
      }
    __syncthreads();
  }
}

// ============================================================
// K2: w = softmax(h @ W2 + b2) via tf32 mma + ldmatrix, softmax in regs.
// ============================================================
__global__ __launch_bounds__(256, 2) void k2_mma(
    const float* __restrict__ W2T, const float* __restrict__ b2) {
  __shared__ float As[2][128][20];
  __shared__ float Bs[2][64][20];
  const int tid = threadIdx.x, wid = tid >> 5, lane = tid & 31;
  const int m0 = blockIdx.x * 128;
  const int g = lane >> 2, t = lane & 3;
  const int lrow = ((lane >> 3) & 1) * 8 + (lane & 7);
  const int lcol = (lane >> 4) * 4;
  const uint32_t sA = smem_u32(&As[0][0][0]);
  const uint32_t sB = smem_u32(&Bs[0][0][0]);

  float acc[8][4];
#pragma unroll
  for (int nt = 0; nt < 8; nt++)
#pragma unroll
    for (int r = 0; r < 4; r++) acc[nt][r] = 0.f;

  auto load = [&](int c, int buf) {
    const int k0 = c * 16;
    const int rowa = tid >> 2, c4 = (tid & 3) * 4;
#pragma unroll
    for (int l = 0; l < 2; l++) {
      const int row = rowa + l * 64;
      CP_A16(sA + (uint32_t)buf * (128 * 20 * 4) + (uint32_t)(row * 20 + c4) * 4,
             g_h + (size_t)(m0 + row) * 128 + k0 + c4);
    }
    if (rowa < 64)
      CP_A16(sB + (uint32_t)buf * (64 * 20 * 4) + (uint32_t)(rowa * 20 + c4) * 4,
             W2T + (size_t)rowa * 128 + k0 + c4);
  };

  load(0, 0);
  CP_COMMIT();
#pragma unroll 1
  for (int c = 0; c < 8; c++) {
    const int buf = c & 1;
    if (c + 1 < 8) { load(c + 1, buf ^ 1); CP_COMMIT(); CP_WAIT1(); }
    else CP_WAIT0();
    __syncthreads();
    const uint32_t ab = sA + (uint32_t)buf * (128 * 20 * 4);
    const uint32_t bb = sB + (uint32_t)buf * (64 * 20 * 4);
#pragma unroll
    for (int ks = 0; ks < 2; ks++) {
      const int kk = ks * 8;
      uint32_t a[4], b[8][2];
      ldsm4(a, ab + (uint32_t)((wid * 16 + lrow) * 20 + kk + lcol) * 4);
#pragma unroll
      for (int p = 0; p < 4; p++) {
        uint32_t t4[4];
        ldsm4(t4, bb + (uint32_t)((p * 16 + lrow) * 20 + kk + lcol) * 4);
        b[2 * p][0] = t4[0]; b[2 * p + 1][0] = t4[1];
        b[2 * p][1] = t4[2]; b[2 * p + 1][1] = t4[3];
      }
#pragma unroll
      for (int nt = 0; nt < 8; nt++) mma_tf32(acc[nt], a, b[nt]);
    }
    __syncthreads();
  }

#pragma unroll
  for (int nt = 0; nt < 8; nt++) {
    float2 bb = *(const float2*)(b2 + nt * 8 + t * 2);
    acc[nt][0] += bb.x; acc[nt][1] += bb.y;
    acc[nt][2] += bb.x; acc[nt][3] += bb.y;
  }
  float m0v = -1e30f, m1v = -1e30f;
#pragma unroll
  for (int nt = 0; nt < 8; nt++) {
    m0v = fmaxf(m0v, fmaxf(acc[nt][0], acc[nt][1]));
    m1v = fmaxf(m1v, fmaxf(acc[nt][2], acc[nt][3]));
  }
#pragma unroll
  for (int o = 1; o <= 2; o <<= 1) {
    m0v = fmaxf(m0v, __shfl_xor_sync(~0u, m0v, o));
    m1v = fmaxf(m1v, __shfl_xor_sync(~0u, m1v, o));
  }
  float s0 = 0.f, s1 = 0.f;
#pragma unroll
  for (int nt = 0; nt < 8; nt++) {
    acc[nt][0] = __expf(acc[nt][0] - m0v); s0 += acc[nt][0];
    acc[nt][1] = __expf(acc[nt][1] - m0v); s0 += acc[nt][1];
    acc[nt][2] = __expf(acc[nt][2] - m1v); s1 += acc[nt][2];
    acc[nt][3] = __expf(acc[nt][3] - m1v); s1 += acc[nt][3];
  }
#pragma unroll
  for (int o = 1; o <= 2; o <<= 1) {
    s0 += __shfl_xor_sync(~0u, s0, o);
    s1 += __shfl_xor_sync(~0u, s1, o);
  }
  const float i0 = 1.f / s0, i1 = 1.f / s1;
  const int r0 = m0 + wid * 16 + g;
#pragma unroll
  for (int nt = 0; nt < 8; nt++) {
    const int col = nt * 8 + t * 2;
    *(float2*)(g_w + (size_t)r0 * 64 + col) =
        make_float2(f2tf32f(acc[nt][0] * i0), f2tf32f(acc[nt][1] * i0));
    *(float2*)(g_w + (size_t)(r0 + 8) * 64 + col) =
        make_float2(f2tf32f(acc[nt][2] * i1), f2tf32f(acc[nt][3] * i1));
  }
}

// ============================================================
// K5a: split-K partials of w^T @ updates via tf32 mma.
// 3-stage cp.async, CUTLASS order (issue -> compute -> wait -> sync).
// ============================================================
__global__ __launch_bounds__(256) void k5a_partials() {
  const int dq    = blockIdx.x & 3;
  const int chunk = blockIdx.x >> 2;
  const int d0 = dq * 128;
  const int b0 = chunk * CHUNK_ROWS;
  __shared__ float wt[3][16][68];
  __shared__ float ut[3][16][132];
  const int tid = threadIdx.x, wid = tid >> 5, lane = tid & 31;
  const int sw = (wid & 1) * 32, dw = (wid >> 1) * 32;
  const int g = lane >> 2, t = lane & 3;
  const uint32_t sW = smem_u32(&wt[0][0][0]);
  const uint32_t sU = smem_u32(&ut[0][0][0]);

  float acc[2][4][4];
#pragma unroll
  for (int mt = 0; mt < 2; mt++)
#pragma unroll
    for (int nt = 0; nt < 4; nt++)
#pragma unroll
      for (int r = 0; r < 4; r++) acc[mt][nt][r] = 0.f;

  auto load = [&](int c, int st) {
    const int k0 = c * 16;
    {
      const int row = tid >> 4, c4 = (tid & 15) * 4;
      CP_A16(sW + (uint32_t)st * (16 * 68 * 4) + (uint32_t)(row * 68 + c4) * 4,
             g_w + (size_t)(b0 + k0 + row) * 64 + c4);
    }
#pragma unroll
    for (int l = 0; l < 2; l++) {
      const int lin = tid + l * 256;
      const int row = lin >> 5, c4 = (lin & 31) * 4;
      CP_A16(sU + (uint32_t)st * (16 * 132 * 4) + (uint32_t)(row * 132 + c4) * 4,
             g_upd + (size_t)(b0 + k0 + row) * 512 + d0 + c4);
    }
  };

  constexpr int NCH = CHUNK_ROWS / 16;
  load(0, 0);
  CP_COMMIT();
  load(1, 1);
  CP_COMMIT();
  CP_WAIT1();
  __syncthreads();
#pragma unroll 1
  for (int c = 0; c < NCH; c++) {
    const int st = c % 3;
    if (c + 2 < NCH) { load(c + 2, (c + 2) % 3); CP_COMMIT(); }
#pragma unroll
    for (int ks = 0; ks < 2; ks++) {
      const int kk = ks * 8;
      uint32_t a[2][4], b[4][2];
#pragma unroll
      for (int mt = 0; mt < 2; mt++) {
        const int sb = sw + mt * 16;
        a[mt][0] = __float_as_uint(wt[st][kk + t][sb + g]);
        a[mt][1] = __float_as_uint(wt[st][kk + t][sb + 8 + g]);
        a[mt][2] = __float_as_uint(wt[st][kk + t + 4][sb + g]);
        a[mt][3] = __float_as_uint(wt[st][kk + t + 4][sb + 8 + g]);
      }
#pragma unroll
      for (int nt = 0; nt < 4; nt++) {
        const int db = dw + nt * 8;
        b[nt][0] = __float_as_uint(ut[st][kk + t][db + g]);
        b[nt][1] = __float_as_uint(ut[st][kk + t + 4][db + g]);
      }
#pragma unroll
      for (int mt = 0; mt < 2; mt++)
#pragma unroll
        for (int nt = 0; nt < 4; nt++) mma_tf32(acc[mt][nt], a[mt], b[nt]);
    }
    if (c + 1 < NCH) {
      if (c + 2 < NCH) CP_WAIT1(); else CP_WAIT0();
      __syncthreads();
    }
  }

  float* p = g_part + (size_t)chunk * (NS * ND);
#pragma unroll
  for (int mt = 0; mt < 2; mt++) {
#pragma unroll
    for (int nt = 0; nt < 4; nt++) {
      const int s = sw + mt * 16 + g;
      const int d = d0 + dw + nt * 8 + t * 2;
      *(float2*)(p + (size_t)s * 512 + d) = make_float2(acc[mt][nt][0], acc[mt][nt][1]);
      *(float2*)(p + (size_t)(s + 8) * 512 + d) = make_float2(acc[mt][nt][2], acc[mt][nt][3]);
    }
  }
}

// ============================================================
// K5b: new_ref = ref + 0.01 * sum(partials)   (deterministic order)
// ============================================================
__global__ __launch_bounds__(256) void k5b_reduce(
    const float* __restrict__ REF, float* __restrict__ OUT_REF) {
  const int idx = blockIdx.x * 256 + threadIdx.x;
  float s = 0.f;
#pragma unroll 8
  for (int c = 0; c < NCHUNK; c++) s += g_part[(size_t)c * (NS * ND) + idx];
  OUT_REF[idx] = REF[idx] + 0.01f * s;
}

// ============================================================
extern "C" void kernel_launch(void* const* d_in, const int* in_sizes, int n_in,
                              void* d_out, int out_size) {
  const float* X   = (const float*)d_in[0];
  const float* REF = (const float*)d_in[1];
  const float* W1  = (const float*)d_in[2];
  const float* b1  = (const float*)d_in[3];
  const float* W2  = (const float*)d_in[4];
  const float* b2  = (const float*)d_in[5];
  const float* WU  = (const float*)d_in[6];
  const float* bu  = (const float*)d_in[7];

  float* out_sel = (float*)d_out;
  float* out_ref = (float*)d_out + (size_t)NB * ND;

  float *w1T, *refT, *w2T, *bt, *rw, *h, *w, *upd;
  cudaGetSymbolAddress((void**)&w1T, g_w1T);
  cudaGetSymbolAddress((void**)&refT, g_refT);
  cudaGetSymbolAddress((void**)&w2T, g_w2T);
  cudaGetSymbolAddress((void**)&bt, g_bt);
  cudaGetSymbolAddress((void**)&rw, g_rw);
  cudaGetSymbolAddress((void**)&h, g_h);
  cudaGetSymbolAddress((void**)&w, g_w);
  cudaGetSymbolAddress((void**)&upd, g_upd);

  static int smem_set = 0;
  if (!smem_set) {
    cudaFuncSetAttribute(k3_select, cudaFuncAttributeMaxDynamicSharedMemorySize, 104448);
    cudaFuncSetAttribute(gemm_mma<1, 512, false, true>,
                         cudaFuncAttributeMaxDynamicSharedMemorySize, 61440);
    cudaFuncSetAttribute(gemm_mma<2, 576, true, true>,
                         cudaFuncAttributeMaxDynamicSharedMemorySize, 61440);
    smem_set = 1;
  }

  dim3 tb(32, 8);
  // weight preprocessing (all tiny)
  k_transpose<<<dim3(4, 16), tb>>>(W1, w1T, 512, 128, 512);    // W1^T tf32
  k_transpose<<<dim3(16, 2), tb>>>(REF, refT, 64, 512, 64);    // ref^T tf32
  k_transpose<<<dim3(2, 4), tb>>>(W2, w2T, 128, 64, 128);      // W2^T tf32
  k_transpose<<<dim3(16, 16), tb>>>(WU, bt, 512, 512, 576);    // Wu1^T -> bt[:, 0:512]
  k_rw<<<8, 256>>>(REF, WU, rw);                               // RW = ref @ Wu2 (f32)
  k_transpose<<<dim3(16, 2), tb>>>(rw, bt + 512, 64, 512, 576);// RW^T -> bt[:, 512:576]

  // K1: h = relu(X @ W1 + b1)   (tf32-rounded store)
  gemm_mma<1, 512, false, true><<<dim3(1, NB / 128), 256, 61440>>>(
      X, nullptr, 512, 0, w1T, b1, h, 128);
  // K2: w = softmax(h @ W2 + b2)
  k2_mma<<<NB / 128, 256>>>(w2T, b2);
  // K3: selected = w @ ref   (one CTA per row-block, n-loop)
  k3_select<<<NB / 128, 256, 104448>>>(refT, out_sel);
  // K4': updates = tanh([X | w] @ [Wu1; RW] + bu)   K=576
  gemm_mma<2, 576, true, true><<<dim3(4, NB / 128), 256, 61440>>>(
      X, w, 512, 64, bt, bu, upd, 512);
  // K5: ref update (deterministic split-K, tensor core)
  k5a_partials<<<NCHUNK * 4, 256>>>();
  k5b_reduce<<<(NS * ND) / 256, 256>>>(REF, out_ref);
}

// round 17
// speedup vs baseline: 1.0572x; 1.0405x over previous
#include <cuda_runtime.h>
#include <math.h>
#include <stdint.h>

#define NB 131072
#define ND 512
#define NS 64
#define NH 128
#define NCHUNK 128
#define CHUNK_ROWS (NB / NCHUNK)   /* 1024 */

// ---- scratch (static device globals; no runtime allocation) ----
static __device__ float g_w[(size_t)NB * NS];             // softmax weights (tf32-rounded)
static __device__ float g_upd[(size_t)NB * ND];           // tanh updates (tf32-rounded)
static __device__ float g_part[(size_t)NCHUNK * NS * ND]; // split-K partials
static __device__ float g_w1T[(size_t)NH * ND];           // [128][512] tf32
static __device__ float g_refT[(size_t)ND * NS];          // [512][64] tf32
static __device__ float g_w2T[(size_t)NS * NH];           // [64][128] tf32
static __device__ float g_bt[(size_t)ND * 576];           // [512 n][576 k] = [Wu1^T | RW^T] tf32
static __device__ float g_rw[(size_t)NS * ND];            // RW = ref @ Wu2  [64][512] f32

// ============================================================
// helpers
// ============================================================
__device__ __forceinline__ float f2tf32f(float x) {
  uint32_t r;
  asm("cvt.rna.tf32.f32 %0, %1;" : "=r"(r) : "f"(x));
  return __uint_as_float(r);
}
__device__ __forceinline__ void mma_tf32(float c[4], const uint32_t a[4],
                                         const uint32_t b[2]) {
  asm volatile(
      "mma.sync.aligned.m16n8k8.row.col.f32.tf32.tf32.f32 "
      "{%0,%1,%2,%3}, {%4,%5,%6,%7}, {%8,%9}, {%0,%1,%2,%3};"
      : "+f"(c[0]), "+f"(c[1]), "+f"(c[2]), "+f"(c[3])
      : "r"(a[0]), "r"(a[1]), "r"(a[2]), "r"(a[3]), "r"(b[0]), "r"(b[1]));
}
__device__ __forceinline__ void ldsm4(uint32_t r[4], uint32_t addr) {
  asm volatile("ldmatrix.sync.aligned.m8n8.x4.shared.b16 {%0,%1,%2,%3}, [%4];"
               : "=r"(r[0]), "=r"(r[1]), "=r"(r[2]), "=r"(r[3]) : "r"(addr));
}
template <int ACT> __device__ __forceinline__ float actf(float x) {
  if (ACT == 1) return x > 0.f ? x : 0.f;
  if (ACT == 2) return tanhf(x);
  return x;
}
#define CP_A16(dst, src)                                              \
  asm volatile("cp.async.cg.shared.global [%0], [%1], 16;"            \
               :: "r"(dst), "l"(__cvta_generic_to_global(src)) : "memory")
#define CP_COMMIT() asm volatile("cp.async.commit_group;" ::: "memory")
#define CP_WAIT0() asm volatile("cp.async.wait_group 0;" ::: "memory")
#define CP_WAIT1() asm volatile("cp.async.wait_group 1;" ::: "memory")

__device__ __forceinline__ uint32_t smem_u32(const void* p) {
  uint32_t a;
  asm("{ .reg .u64 t; cvta.to.shared.u64 t, %1; cvt.u32.u64 %0, t; }"
      : "=r"(a) : "l"(p));
  return a;
}

// ============================================================
// 32x32 transpose + tf32 round: dst[c*dst_stride + r] = tf32(src[r][c])
// ============================================================
__global__ void k_transpose(const float* __restrict__ src, float* __restrict__ dst,
                            int R, int C, int dst_stride) {
  __shared__ float t[32][33];
  int c0 = blockIdx.x * 32, r0 = blockIdx.y * 32;
  int x = threadIdx.x, y = threadIdx.y;
#pragma unroll
  for (int i = 0; i < 32; i += 8)
    t[y + i][x] = src[(size_t)(r0 + y + i) * C + c0 + x];
  __syncthreads();
#pragma unroll
  for (int i = 0; i < 32; i += 8)
    dst[(size_t)(c0 + y + i) * dst_stride + r0 + x] = f2tf32f(t[x][y + i]);
}

// ============================================================
// RW = ref @ Wu2  (f32 FFMA; tiny: 64x512x512)
// ============================================================
__global__ __launch_bounds__(256) void k_rw(
    const float* __restrict__ REF, const float* __restrict__ WU,
    float* __restrict__ RW) {
  __shared__ float rs[64][17];
  __shared__ float us[16][68];
  const int tid = threadIdx.x;
  const int n0 = blockIdx.x * 64;
  const int si = (tid >> 4) * 4, ni = (tid & 15) * 4;
  float acc[4][4];
#pragma unroll
  for (int i = 0; i < 4; i++)
#pragma unroll
    for (int j = 0; j < 4; j++) acc[i][j] = 0.f;

  for (int k0 = 0; k0 < 512; k0 += 16) {
    {
      int s = tid >> 2, c4 = (tid & 3) * 4;
      float4 v = *(const float4*)(REF + (size_t)s * 512 + k0 + c4);
      rs[s][c4] = v.x; rs[s][c4 + 1] = v.y; rs[s][c4 + 2] = v.z; rs[s][c4 + 3] = v.w;
    }
    {
      int r = tid >> 4, c4 = (tid & 15) * 4;
      float4 v = *(const float4*)(WU + (size_t)(512 + k0 + r) * 512 + n0 + c4);
      us[r][c4] = v.x; us[r][c4 + 1] = v.y; us[r][c4 + 2] = v.z; us[r][c4 + 3] = v.w;
    }
    __syncthreads();
#pragma unroll
    for (int kk = 0; kk < 16; kk++) {
#pragma unroll
      for (int i = 0; i < 4; i++) {
        float r = rs[si + i][kk];
#pragma unroll
        for (int j = 0; j < 4; j++) acc[i][j] = fmaf(r, us[kk][ni + j], acc[i][j]);
      }
    }
    __syncthreads();
  }
#pragma unroll
  for (int i = 0; i < 4; i++)
#pragma unroll
    for (int j = 0; j < 4; j++)
      RW[(size_t)(si + i) * 512 + n0 + ni + j] = acc[i][j];
}

// ============================================================
// tf32 mma.sync GEMM (K4'): cp.async 2-stage + ldmatrix fragments
// (round-13 proven structure, static smem)
// ============================================================
template <int ACT, int KTOT, bool ASPLIT, bool CVT_A>
__global__ __launch_bounds__(256, 2) void gemm_mma(
    const float* __restrict__ A0, const float* __restrict__ A1,
    int a_stride, int a1_stride,
    const float* __restrict__ BT, const float* __restrict__ bias,
    float* __restrict__ OUT, int o_stride) {
  __shared__ float As[2][128][20];
  __shared__ float Bs[2][128][20];
  const int tid = threadIdx.x, wid = tid >> 5, lane = tid & 31;
  const int n0 = blockIdx.x * 128;
  const int m0 = blockIdx.y * 128;
  const int wm = (wid & 3) * 32;
  const int wn = (wid >> 2) * 64;
  const int g = lane >> 2, t = lane & 3;
  const int lrow = ((lane >> 3) & 1) * 8 + (lane & 7);
  const int lcol = (lane >> 4) * 4;

  const uint32_t sA = smem_u32(&As[0][0][0]);
  const uint32_t sB = smem_u32(&Bs[0][0][0]);
  const int row_l = tid >> 2;
  const int c4_l = (tid & 3) * 4;

  float acc[2][8][4];
#pragma unroll
  for (int mt = 0; mt < 2; mt++)
#pragma unroll
    for (int nt = 0; nt < 8; nt++)
#pragma unroll
      for (int r = 0; r < 4; r++) acc[mt][nt][r] = 0.f;

  auto load_tiles = [&](int c, int buf) {
    const int k0 = c * 16;
    const float* Asrc = (!ASPLIT || k0 < 512) ? A0 : A1;
    const int ko = (!ASPLIT || k0 < 512) ? k0 : k0 - 512;
    const int ast = (!ASPLIT || k0 < 512) ? a_stride : a1_stride;
    const uint32_t da = sA + (uint32_t)buf * (128 * 20 * 4);
    const uint32_t db = sB + (uint32_t)buf * (128 * 20 * 4);
#pragma unroll
    for (int l = 0; l < 2; l++) {
      const int row = row_l + l * 64;
      CP_A16(da + (uint32_t)(row * 20 + c4_l) * 4,
             Asrc + (size_t)(m0 + row) * ast + ko + c4_l);
      CP_A16(db + (uint32_t)(row * 20 + c4_l) * 4,
             BT + (size_t)(n0 + row) * KTOT + k0 + c4_l);
    }
  };

  constexpr int NCH = KTOT / 16;
  load_tiles(0, 0);
  CP_COMMIT();
#pragma unroll 1
  for (int c = 0; c < NCH; c++) {
    const int buf = c & 1;
    if (c + 1 < NCH) {
      load_tiles(c + 1, buf ^ 1);
      CP_COMMIT();
      CP_WAIT1();
    } else {
      CP_WAIT0();
    }
    __syncthreads();
    const uint32_t ab = sA + (uint32_t)buf * (128 * 20 * 4);
    const uint32_t bb = sB + (uint32_t)buf * (128 * 20 * 4);
#pragma unroll
    for (int ks = 0; ks < 2; ks++) {
      const int kk = ks * 8;
      uint32_t a[2][4], b[8][2];
#pragma unroll
      for (int mt = 0; mt < 2; mt++) {
        ldsm4(a[mt], ab + (uint32_t)((wm + mt * 16 + lrow) * 20 + kk + lcol) * 4);
        if (CVT_A) {
#pragma unroll
          for (int r = 0; r < 4; r++)
            a[mt][r] = __float_as_uint(f2tf32f(__uint_as_float(a[mt][r])));
        }
      }
#pragma unroll
      for (int p = 0; p < 4; p++) {
        uint32_t t4[4];
        ldsm4(t4, bb + (uint32_t)((wn + p * 16 + lrow) * 20 + kk + lcol) * 4);
        b[2 * p][0] = t4[0]; b[2 * p + 1][0] = t4[1];
        b[2 * p][1] = t4[2]; b[2 * p + 1][1] = t4[3];
      }
#pragma unroll
      for (int mt = 0; mt < 2; mt++)
#pragma unroll
        for (int nt = 0; nt < 8; nt++) mma_tf32(acc[mt][nt], a[mt], b[nt]);
    }
    __syncthreads();
  }

#pragma unroll
  for (int mt = 0; mt < 2; mt++) {
#pragma unroll
    for (int nt = 0; nt < 8; nt++) {
      const int row = m0 + wm + mt * 16 + g;
      const int col = n0 + wn + nt * 8 + t * 2;
      float b0 = 0.f, b1 = 0.f;
      if (bias) { b0 = bias[col]; b1 = bias[col + 1]; }
      float r0 = actf<ACT>(acc[mt][nt][0] + b0);
      float r1 = actf<ACT>(acc[mt][nt][1] + b1);
      float r2 = actf<ACT>(acc[mt][nt][2] + b0);
      float r3 = actf<ACT>(acc[mt][nt][3] + b1);
      if (ACT != 0) { r0 = f2tf32f(r0); r1 = f2tf32f(r1); r2 = f2tf32f(r2); r3 = f2tf32f(r3); }
      *(float2*)(OUT + (size_t)row * o_stride + col) = make_float2(r0, r1);
      *(float2*)(OUT + (size_t)(row + 8) * o_stride + col) = make_float2(r2, r3);
    }
  }
}

// ============================================================
// k12: fused K1+K2 (round-10 verified-correct version).
// Mainloop: h_tile[128x128] = X[m0..][0..512) @ W1T  (tf32 mma).
// Epilogue: relu+bias+tf32 -> stage halves to smem -> mma vs W2T ->
//           softmax in regs -> g_w.  Dynamic smem 68608B.
// ============================================================
__global__ __launch_bounds__(256, 2) void k12(
    const float* __restrict__ X, const float* __restrict__ W1T,
    const float* __restrict__ b1, const float* __restrict__ W2T,
    const float* __restrict__ b2) {
  extern __shared__ char dsm[];
  const uint32_t sA = smem_u32(dsm);
  const uint32_t sB = sA + 20480;
  const uint32_t sH = sA;                 // epilogue: h half [128][68]
  const uint32_t sW2 = sA + 34816;        // epilogue: W2T [64][132]
  float* hs = (float*)dsm;

  const int tid = threadIdx.x, wid = tid >> 5, lane = tid & 31;
  const int m0 = blockIdx.x * 128;
  const int wm = (wid & 3) * 32;
  const int wn = (wid >> 2) * 64;
  const int g = lane >> 2, t = lane & 3;
  const int lrow = ((lane >> 3) & 1) * 8 + (lane & 7);
  const int lcol = (lane >> 4) * 4;
  const int row_l = tid >> 2;
  const int c4_l = (tid & 3) * 4;

  float acc[2][8][4];
#pragma unroll
  for (int mt = 0; mt < 2; mt++)
#pragma unroll
    for (int nt = 0; nt < 8; nt++)
#pragma unroll
      for (int r = 0; r < 4; r++) acc[mt][nt][r] = 0.f;

  auto load_tiles = [&](int c, int buf) {
    const int k0 = c * 16;
    const uint32_t da = sA + (uint32_t)buf * (128 * 20 * 4);
    const uint32_t db = sB + (uint32_t)buf * (128 * 20 * 4);
#pragma unroll
    for (int l = 0; l < 2; l++) {
      const int row = row_l + l * 64;
      CP_A16(da + (uint32_t)(row * 20 + c4_l) * 4,
             X + (size_t)(m0 + row) * 512 + k0 + c4_l);
      CP_A16(db + (uint32_t)(row * 20 + c4_l) * 4,
             W1T + (size_t)row * 512 + k0 + c4_l);
    }
  };

  load_tiles(0, 0);
  CP_COMMIT();
#pragma unroll 1
  for (int c = 0; c < 32; c++) {
    const int buf = c & 1;
    if (c + 1 < 32) { load_tiles(c + 1, buf ^ 1); CP_COMMIT(); CP_WAIT1(); }
    else CP_WAIT0();
    __syncthreads();
    const uint32_t ab = sA + (uint32_t)buf * (128 * 20 * 4);
    const uint32_t bb = sB + (uint32_t)buf * (128 * 20 * 4);
#pragma unroll
    for (int ks = 0; ks < 2; ks++) {
      const int kk = ks * 8;
      uint32_t a[2][4], b[8][2];
#pragma unroll
      for (int mt = 0; mt < 2; mt++) {
        ldsm4(a[mt], ab + (uint32_t)((wm + mt * 16 + lrow) * 20 + kk + lcol) * 4);
#pragma unroll
        for (int r = 0; r < 4; r++)
          a[mt][r] = __float_as_uint(f2tf32f(__uint_as_float(a[mt][r])));
      }
#pragma unroll
      for (int p = 0; p < 4; p++) {
        uint32_t t4[4];
        ldsm4(t4, bb + (uint32_t)((wn + p * 16 + lrow) * 20 + kk + lcol) * 4);
        b[2 * p][0] = t4[0]; b[2 * p + 1][0] = t4[1];
        b[2 * p][1] = t4[2]; b[2 * p + 1][1] = t4[3];
      }
#pragma unroll
      for (int mt = 0; mt < 2; mt++)
#pragma unroll
        for (int nt = 0; nt < 8; nt++) mma_tf32(acc[mt][nt], a[mt], b[nt]);
    }
    __syncthreads();
  }

  // ---- epilogue: relu + tf32 round (in regs) ----
#pragma unroll
  for (int mt = 0; mt < 2; mt++)
#pragma unroll
    for (int nt = 0; nt < 8; nt++) {
      const int col = wn + nt * 8 + t * 2;
      float b0 = b1[col], bb1 = b1[col + 1];
      acc[mt][nt][0] = f2tf32f(fmaxf(acc[mt][nt][0] + b0, 0.f));
      acc[mt][nt][1] = f2tf32f(fmaxf(acc[mt][nt][1] + bb1, 0.f));
      acc[mt][nt][2] = f2tf32f(fmaxf(acc[mt][nt][2] + b0, 0.f));
      acc[mt][nt][3] = f2tf32f(fmaxf(acc[mt][nt][3] + bb1, 0.f));
    }
  // load W2T [64][128] into smem (region disjoint from h staging)
  {
#pragma unroll
    for (int i = 0; i < 8; i++) {
      const int idx = tid + i * 256;
      const int row = idx >> 5, c4 = (idx & 31) * 4;
      CP_A16(sW2 + (uint32_t)(row * 132 + c4) * 4, W2T + (size_t)row * 128 + c4);
    }
    CP_COMMIT();
  }

  float lg[8][4];
#pragma unroll
  for (int nt = 0; nt < 8; nt++)
#pragma unroll
    for (int r = 0; r < 4; r++) lg[nt][r] = 0.f;

#pragma unroll 1
  for (int half = 0; half < 2; half++) {
    if ((wid >> 2) == half) {   // this warp's cols are in this half
#pragma unroll
      for (int mt = 0; mt < 2; mt++)
#pragma unroll
        for (int nt = 0; nt < 8; nt++) {
          const int row = wm + mt * 16 + g;
          const int coll = (wn & 63) + nt * 8 + t * 2;
          *(float2*)&hs[row * 68 + coll] = make_float2(acc[mt][nt][0], acc[mt][nt][1]);
          *(float2*)&hs[(row + 8) * 68 + coll] = make_float2(acc[mt][nt][2], acc[mt][nt][3]);
        }
    }
    if (half == 0) CP_WAIT0();
    __syncthreads();
#pragma unroll
    for (int ks = 0; ks < 8; ks++) {
      const int kk = ks * 8;
      uint32_t a[4], b[8][2];
      ldsm4(a, sH + (uint32_t)((wid * 16 + lrow) * 68 + kk + lcol) * 4);
#pragma unroll
      for (int p = 0; p < 4; p++) {
        uint32_t t4[4];
        ldsm4(t4, sW2 + (uint32_t)((p * 16 + lrow) * 132 + half * 64 + kk + lcol) * 4);
        b[2 * p][0] = t4[0]; b[2 * p + 1][0] = t4[1];
        b[2 * p][1] = t4[2]; b[2 * p + 1][1] = t4[3];
      }
#pragma unroll
      for (int nt = 0; nt < 8; nt++) mma_tf32(lg[nt], a, b[nt]);
    }
    __syncthreads();
  }

  // bias + softmax (rows wid*16+g, wid*16+8+g)
#pragma unroll
  for (int nt = 0; nt < 8; nt++) {
    float2 bb = *(const float2*)(b2 + nt * 8 + t * 2);
    lg[nt][0] += bb.x; lg[nt][1] += bb.y;
    lg[nt][2] += bb.x; lg[nt][3] += bb.y;
  }
  float m0v = -1e30f, m1v = -1e30f;
#pragma unroll
  for (int nt = 0; nt < 8; nt++) {
    m0v = fmaxf(m0v, fmaxf(lg[nt][0], lg[nt][1]));
    m1v = fmaxf(m1v, fmaxf(lg[nt][2], lg[nt][3]));
  }
#pragma unroll
  for (int o = 1; o <= 2; o <<= 1) {
    m0v = fmaxf(m0v, __shfl_xor_sync(~0u, m0v, o));
    m1v = fmaxf(m1v, __shfl_xor_sync(~0u, m1v, o));
  }
  float s0 = 0.f, s1 = 0.f;
#pragma unroll
  for (int nt = 0; nt < 8; nt++) {
    lg[nt][0] = __expf(lg[nt][0] - m0v); s0 += lg[nt][0];
    lg[nt][1] = __expf(lg[nt][1] - m0v); s0 += lg[nt][1];
    lg[nt][2] = __expf(lg[nt][2] - m1v); s1 += lg[nt][2];
    lg[nt][3] = __expf(lg[nt][3] - m1v); s1 += lg[nt][3];
  }
#pragma unroll
  for (int o = 1; o <= 2; o <<= 1) {
    s0 += __shfl_xor_sync(~0u, s0, o);
    s1 += __shfl_xor_sync(~0u, s1, o);
  }
  const float i0 = 1.f / s0, i1 = 1.f / s1;
  const int r0 = m0 + wid * 16 + g;
#pragma unroll
  for (int nt = 0; nt < 8; nt++) {
    const int col = nt * 8 + t * 2;
    *(float2*)(g_w + (size_t)r0 * 64 + col) =
        make_float2(f2tf32f(lg[nt][0] * i0), f2tf32f(lg[nt][1] * i0));
    *(float2*)(g_w + (size_t)(r0 + 8) * 64 + col) =
        make_float2(f2tf32f(lg[nt][2] * i1), f2tf32f(lg[nt][3] * i1));
  }
}

// ============================================================
// k3_select: selected = w @ ref.  One CTA per 128-row block (grid 1024).
// ============================================================
__global__ __launch_bounds__(256, 2) void k3_select(
    const float* __restrict__ REFT, float* __restrict__ OUT) {
  extern __shared__ char dsm[];
  const uint32_t sA = smem_u32(dsm);           // [128][68]
  const uint32_t sB = sA + 34816;              // 2 x [128][68]
  const int tid = threadIdx.x, wid = tid >> 5, lane = tid & 31;
  const int m0 = blockIdx.x * 128;
  const int wm = (wid & 3) * 32;
  const int wn = (wid >> 2) * 64;
  const int g = lane >> 2, t = lane & 3;
  const int lrow = ((lane >> 3) & 1) * 8 + (lane & 7);
  const int lcol = (lane >> 4) * 4;

#pragma unroll
  for (int i = 0; i < 8; i++) {
    const int idx = tid + i * 256;
    const int row = idx >> 4, c4 = (idx & 15) * 4;
    CP_A16(sA + (uint32_t)(row * 68 + c4) * 4, g_w + (size_t)(m0 + row) * 64 + c4);
  }
  auto loadB = [&](int nc, int buf) {
#pragma unroll
    for (int i = 0; i < 8; i++) {
      const int idx = tid + i * 256;
      const int row = idx >> 4, c4 = (idx & 15) * 4;
      CP_A16(sB + (uint32_t)buf * 34816 + (uint32_t)(row * 68 + c4) * 4,
             REFT + (size_t)(nc * 128 + row) * 64 + c4);
    }
  };
  loadB(0, 0);
  CP_COMMIT();

#pragma unroll 1
  for (int nc = 0; nc < 4; nc++) {
    const int buf = nc & 1;
    if (nc + 1 < 4) { loadB(nc + 1, buf ^ 1); CP_COMMIT(); CP_WAIT1(); }
    else CP_WAIT0();
    __syncthreads();

    float acc[2][8][4];
#pragma unroll
    for (int mt = 0; mt < 2; mt++)
#pragma unroll
      for (int nt = 0; nt < 8; nt++)
#pragma unroll
        for (int r = 0; r < 4; r++) acc[mt][nt][r] = 0.f;

    const uint32_t bb = sB + (uint32_t)buf * 34816;
#pragma unroll
    for (int ks = 0; ks < 8; ks++) {
      const int kk = ks * 8;
      uint32_t a[2][4], b[8][2];
#pragma unroll
      for (int mt = 0; mt < 2; mt++)
        ldsm4(a[mt], sA + (uint32_t)((wm + mt * 16 + lrow) * 68 + kk + lcol) * 4);
#pragma unroll
      for (int p = 0; p < 4; p++) {
        uint32_t t4[4];
        ldsm4(t4, bb + (uint32_t)((wn + p * 16 + lrow) * 68 + kk + lcol) * 4);
        b[2 * p][0] = t4[0]; b[2 * p + 1][0] = t4[1];
        b[2 * p][1] = t4[2]; b[2 * p + 1][1] = t4[3];
      }
#pragma unroll
      for (int mt = 0; mt < 2; mt++)
#pragma unroll
        for (int nt = 0; nt < 8; nt++) mma_tf32(acc[mt][nt], a[mt], b[nt]);
    }
#pragma unroll
    for (int mt = 0; mt < 2; mt++)
#pragma unroll
      for (int nt = 0; nt < 8; nt++) {
        const int row = m0 + wm + mt * 16 + g;
        const int col = nc * 128 + wn + nt * 8 + t * 2;
        *(float2*)(OUT + (size_t)row * 512 + col) =
            make_float2(acc[mt][nt][0], acc[mt][nt][1]);
        *(float2*)(OUT + (size_t)(row + 8) * 512 + col) =
            make_float2(acc[mt][nt][2], acc[mt][nt][3]);
      }
    __syncthreads();
  }
}

// ============================================================
// K5a: split-K partials of w^T @ updates via tf32 mma (round-13 2-stage).
// ============================================================
__global__ __launch_bounds__(256) void k5a_partials() {
  const int dq    = blockIdx.x & 3;
  const int chunk = blockIdx.x >> 2;
  const int d0 = dq * 128;
  const int b0 = chunk * CHUNK_ROWS;
  __shared__ float wt[2][16][68];
  __shared__ float ut[2][16][132];
  const int tid = threadIdx.x, wid = tid >> 5, lane = tid & 31;
  const int sw = (wid & 1) * 32, dw = (wid >> 1) * 32;
  const int g = lane >> 2, t = lane & 3;
  const uint32_t sW = smem_u32(&wt[0][0][0]);
  const uint32_t sU = smem_u32(&ut[0][0][0]);

  float acc[2][4][4];
#pragma unroll
  for (int mt = 0; mt < 2; mt++)
#pragma unroll
    for (int nt = 0; nt < 4; nt++)
#pragma unroll
      for (int r = 0; r < 4; r++) acc[mt][nt][r] = 0.f;

  auto load = [&](int c, int buf) {
    const int k0 = c * 16;
    {
      const int row = tid >> 4, c4 = (tid & 15) * 4;
      CP_A16(sW + (uint32_t)buf * (16 * 68 * 4) + (uint32_t)(row * 68 + c4) * 4,
             g_w + (size_t)(b0 + k0 + row) * 64 + c4);
    }
#pragma unroll
    for (int l = 0; l < 2; l++) {
      const int lin = tid + l * 256;
      const int row = lin >> 5, c4 = (lin & 31) * 4;
      CP_A16(sU + (uint32_t)buf * (16 * 132 * 4) + (uint32_t)(row * 132 + c4) * 4,
             g_upd + (size_t)(b0 + k0 + row) * 512 + d0 + c4);
    }
  };

  constexpr int NCH = CHUNK_ROWS / 16;
  load(0, 0);
  CP_COMMIT();
#pragma unroll 1
  for (int c = 0; c < NCH; c++) {
    const int buf = c & 1;
    if (c + 1 < NCH) { load(c + 1, buf ^ 1); CP_COMMIT(); CP_WAIT1(); }
    else CP_WAIT0();
    __syncthreads();
#pragma unroll
    for (int ks = 0; ks < 2; ks++) {
      const int kk = ks * 8;
      uint32_t a[2][4], b[4][2];
#pragma unroll
      for (int mt = 0; mt < 2; mt++) {
        const int sb = sw + mt * 16;
        a[mt][0] = __float_as_uint(wt[buf][kk + t][sb + g]);
        a[mt][1] = __float_as_uint(wt[buf][kk + t][sb + 8 + g]);
        a[mt][2] = __float_as_uint(wt[buf][kk + t + 4][sb + g]);
        a[mt][3] = __float_as_uint(wt[buf][kk + t + 4][sb + 8 + g]);
      }
#pragma unroll
      for (int nt = 0; nt < 4; nt++) {
        const int db = dw + nt * 8;
        b[nt][0] = __float_as_uint(ut[buf][kk + t][db + g]);
        b[nt][1] = __float_as_uint(ut[buf][kk + t + 4][db + g]);
      }
#pragma unroll
      for (int mt = 0; mt < 2; mt++)
#pragma unroll
        for (int nt = 0; nt < 4; nt++) mma_tf32(acc[mt][nt], a[mt], b[nt]);
    }
    __syncthreads();
  }

  float* p = g_part + (size_t)chunk * (NS * ND);
#pragma unroll
  for (int mt = 0; mt < 2; mt++) {
#pragma unroll
    for (int nt = 0; nt < 4; nt++) {
      const int s = sw + mt * 16 + g;
      const int d = d0 + dw + nt * 8 + t * 2;
      *(float2*)(p + (size_t)s * 512 + d) = make_float2(acc[mt][nt][0], acc[mt][nt][1]);
      *(float2*)(p + (size_t)(s + 8) * 512 + d) = make_float2(acc[mt][nt][2], acc[mt][nt][3]);
    }
  }
}

// ============================================================
// K5b: new_ref = ref + 0.01 * sum(partials)   (deterministic order)
// ============================================================
__global__ __launch_bounds__(256) void k5b_reduce(
    const float* __restrict__ REF, float* __restrict__ OUT_REF) {
  const int idx = blockIdx.x * 256 + threadIdx.x;
  float s = 0.f;
#pragma unroll 8
  for (int c = 0; c < NCHUNK; c++) s += g_part[(size_t)c * (NS * ND) + idx];
  OUT_REF[idx] = REF[idx] + 0.01f * s;
}

// ============================================================
extern "C" void kernel_launch(void* const* d_in, const int* in_sizes, int n_in,
                              void* d_out, int out_size) {
  const float* X   = (const float*)d_in[0];
  const float* REF = (const float*)d_in[1];
  const float* W1  = (const float*)d_in[2];
  const float* b1  = (const float*)d_in[3];
  const float* W2  = (const float*)d_in[4];
  const float* b2  = (const float*)d_in[5];
  const float* WU  = (const float*)d_in[6];
  const float* bu  = (const float*)d_in[7];

  float* out_sel = (float*)d_out;
  float* out_ref = (float*)d_out + (size_t)NB * ND;

  float *w1T, *refT, *w2T, *bt, *rw, *w, *upd;
  cudaGetSymbolAddress((void**)&w1T, g_w1T);
  cudaGetSymbolAddress((void**)&refT, g_refT);
  cudaGetSymbolAddress((void**)&w2T, g_w2T);
  cudaGetSymbolAddress((void**)&bt, g_bt);
  cudaGetSymbolAddress((void**)&rw, g_rw);
  cudaGetSymbolAddress((void**)&w, g_w);
  cudaGetSymbolAddress((void**)&upd, g_upd);

  static int smem_set = 0;
  if (!smem_set) {
    cudaFuncSetAttribute(k3_select, cudaFuncAttributeMaxDynamicSharedMemorySize, 104448);
    cudaFuncSetAttribute(k12, cudaFuncAttributeMaxDynamicSharedMemorySize, 68608);
    smem_set = 1;
  }

  dim3 tb(32, 8);
  // weight preprocessing (all tiny)
  k_transpose<<<dim3(4, 16), tb>>>(W1, w1T, 512, 128, 512);    // W1^T tf32
  k_transpose<<<dim3(16, 2), tb>>>(REF, refT, 64, 512, 64);    // ref^T tf32
  k_transpose<<<dim3(2, 4), tb>>>(W2, w2T, 128, 64, 128);      // W2^T tf32
  k_transpose<<<dim3(16, 16), tb>>>(WU, bt, 512, 512, 576);    // Wu1^T -> bt[:, 0:512]
  k_rw<<<8, 256>>>(REF, WU, rw);                               // RW = ref @ Wu2 (f32)
  k_transpose<<<dim3(16, 2), tb>>>(rw, bt + 512, 64, 512, 576);// RW^T -> bt[:, 512:576]

  // K1+K2 fused: w = softmax(relu(X@W1+b1) @ W2 + b2)   (no g_h)
  k12<<<NB / 128, 256, 68608>>>(X, w1T, b1, w2T, b2);
  // K3: selected = w @ ref   (one CTA per row-block, n-loop)
  k3_select<<<NB / 128, 256, 104448>>>(refT, out_sel);
  // K4': updates = tanh([X | w] @ [Wu1; RW] + bu)   K=576
  gemm_mma<2, 576, true, true><<<dim3(4, NB / 128), 256>>>(
      X, w, 512, 64, bt, bu, upd, 512);
  // K5: ref update (deterministic split-K, tensor core)
  k5a_partials<<<NCHUNK * 4, 256>>>();
  k5b_reduce<<<(NS * ND) / 256, 256>>>(REF, out_ref);
}